// round 3
// baseline (speedup 1.0000x reference)
#include <cuda_runtime.h>
#include <cuda_bf16.h>

#define N_PROP 128
#define N_GRIDP 216
#define G_TOT  27648
#define N_KEY  4096
#define C_FEAT 128
#define NS     16
#define K_RED  27648
#define KSPLIT 32

// ---------------- scratch ----------------
static __device__ float  d_grid[G_TOT * 3];
static __device__ float2 d_A[2][N_KEY * 32];
static __device__ int    d_idx[2][G_TOT * NS];
static __device__ float  d_perm[N_PROP * K_RED];
static __device__ float  d_partial[KSPLIT][N_PROP * 256];
static __device__ float  d_hbuf[N_PROP * 256];

// ---------------- f32x2 helpers ----------------
__device__ __forceinline__ unsigned long long pack2(float x, float y) {
    unsigned long long r;
    asm("mov.b64 %0, {%1, %2};" : "=l"(r) : "f"(x), "f"(y));
    return r;
}
__device__ __forceinline__ void fma2(unsigned long long& acc, unsigned long long a, unsigned long long b) {
    asm("fma.rn.f32x2 %0, %1, %2, %0;" : "+l"(acc) : "l"(a), "l"(b));
}
__device__ __forceinline__ float2 unpack2(unsigned long long v) {
    float lo, hi;
    asm("mov.b64 {%0, %1}, %2;" : "=f"(lo), "=f"(hi) : "l"(v));
    return make_float2(lo, hi);
}

// ---------------- k1: grid points ----------------
__global__ void k_grid(const float* __restrict__ wlh, const float* __restrict__ center,
                       const float* __restrict__ yaw, const float* __restrict__ u)
{
    int g = blockIdx.x * 256 + threadIdx.x;
    if (g >= G_TOT) return;
    int ni = g / N_GRIDP;
    float gx = __fmul_rn(u[g * 3 + 0], wlh[ni * 3 + 0]);
    float gy = __fmul_rn(u[g * 3 + 1], wlh[ni * 3 + 1]);
    float gz = __fmul_rn(u[g * 3 + 2], wlh[ni * 3 + 2]);
    float yv = yaw[ni];
    float c = cosf(yv), s = sinf(yv);
    float rx = __fadd_rn(__fmul_rn(c, gx), __fmul_rn(-s, gy));
    float ry = __fadd_rn(__fmul_rn(s, gx), __fmul_rn(c, gy));
    d_grid[g * 3 + 0] = __fadd_rn(rx, center[ni * 3 + 0]);
    d_grid[g * 3 + 1] = __fadd_rn(ry, center[ni * 3 + 1]);
    d_grid[g * 3 + 2] = __fadd_rn(gz, center[ni * 3 + 2]);
}

// ---------------- k2: per-keypoint A = kp.w1[:3] + kf.w1[3:] ----------------
__global__ void __launch_bounds__(256) k_A(const float* __restrict__ kp, const float* __restrict__ kf,
                                           const float* __restrict__ w1_0, const float* __restrict__ w1_1)
{
    __shared__ float w1s[64 * 131];
    const float* w1 = blockIdx.y ? w1_1 : w1_0;
    int tid = threadIdx.y * 32 + threadIdx.x;
    for (int i = tid; i < 64 * 131; i += 256) w1s[i] = w1[i];
    __syncthreads();

    int l = threadIdx.x;
    int kbase = blockIdx.x * 256;
    for (int t = 0; t < 32; t++) {
        int k = kbase + t * 8 + threadIdx.y;
        float kx = kp[k * 3 + 0], ky = kp[k * 3 + 1], kz = kp[k * 3 + 2];
        float a0 = w1s[l * 131 + 0] * kx + w1s[l * 131 + 1] * ky + w1s[l * 131 + 2] * kz;
        float a1 = w1s[(l + 32) * 131 + 0] * kx + w1s[(l + 32) * 131 + 1] * ky + w1s[(l + 32) * 131 + 2] * kz;
#pragma unroll 4
        for (int c = 0; c < C_FEAT; c++) {
            float f = kf[c * N_KEY + k];
            a0 = fmaf(f, w1s[l * 131 + 3 + c], a0);
            a1 = fmaf(f, w1s[(l + 32) * 131 + 3 + c], a1);
        }
        d_A[blockIdx.y][k * 32 + l] = make_float2(a0, a1);
    }
}

// ---------------- k3: ball query, both radii in one scan ----------------
__global__ void __launch_bounds__(128) k_ball(const float* __restrict__ kp)
{
    __shared__ float kxs[N_KEY], kys[N_KEY], kzs[N_KEY];
    for (int i = threadIdx.x; i < N_KEY; i += 128) {
        kxs[i] = kp[i * 3 + 0];
        kys[i] = kp[i * 3 + 1];
        kzs[i] = kp[i * 3 + 2];
    }
    __syncthreads();

    int g = blockIdx.x * 128 + threadIdx.x;
    float gx = d_grid[g * 3 + 0], gy = d_grid[g * 3 + 1], gz = d_grid[g * 3 + 2];
    float gs = __fadd_rn(__fadd_rn(__fmul_rn(gx, gx), __fmul_rn(gy, gy)), __fmul_rn(gz, gz));

    int c0 = 0, c1 = 0, f0 = 0, f1 = 0;
    int* o0 = &d_idx[0][g * NS];
    int* o1 = &d_idx[1][g * NS];

    for (int k = 0; k < N_KEY; k++) {
        float kx = kxs[k], ky = kys[k], kz = kzs[k];
        float ksq = __fadd_rn(__fadd_rn(__fmul_rn(kx, kx), __fmul_rn(ky, ky)), __fmul_rn(kz, kz));
        float dot = __fadd_rn(__fadd_rn(__fmul_rn(gx, kx), __fmul_rn(gy, ky)), __fmul_rn(gz, kz));
        float d2 = __fsub_rn(__fadd_rn(gs, ksq), __fmul_rn(2.0f, dot));
        if (d2 < 2.56f) {
            if (c1 < NS) { if (c1 == 0) f1 = k; o1[c1++] = k; }
            if (d2 < 0.64f) {
                if (c0 == 0) f0 = k;
                o0[c0++] = k;
                if (c0 == NS) break;   // r0 hits are subset of r1 hits -> c1 full too
            }
        }
    }
    for (int n = c1; n < NS; n++) o1[n] = f1;
    for (int n = c0; n < NS; n++) o0[n] = f0;
}

// ---------------- k4: branch MLP + maxpool, warp per grid point ----------------
__global__ void __launch_bounds__(256, 1) k_branch(
    const float* __restrict__ w1_0, const float* __restrict__ g1_0, const float* __restrict__ b1_0,
    const float* __restrict__ w2_0, const float* __restrict__ g2_0, const float* __restrict__ b2_0,
    const float* __restrict__ w1_1, const float* __restrict__ g1_1, const float* __restrict__ b1_1,
    const float* __restrict__ w2_1, const float* __restrict__ g2_1, const float* __restrict__ b2_1)
{
    const int b = blockIdx.y;
    const float* w1 = b ? w1_1 : w1_0;
    const float* g1 = b ? g1_1 : g1_0;
    const float* b1 = b ? b1_1 : b1_0;
    const float* w2 = b ? w2_1 : w2_0;
    const float* g2 = b ? g2_1 : g2_0;
    const float* b2 = b ? b2_1 : b2_0;

    const int lane = threadIdx.x & 31;
    const int warp = threadIdx.x >> 5;

    __shared__ __align__(16) float hbuf[8][64];
    float* hb = hbuf[warp];
    const float4* hb4 = (const float4*)hb;

    // w2 rows for outputs o=lane and o=lane+32, packed (c,c+1) f32x2 pairs
    unsigned long long w2lo[32], w2hi[32];
#pragma unroll
    for (int jj = 0; jj < 32; jj++) {
        float2 vlo = ((const float2*)w2)[lane * 32 + jj];
        float2 vhi = ((const float2*)w2)[(lane + 32) * 32 + jj];
        w2lo[jj] = pack2(vlo.x, vlo.y);
        w2hi[jj] = pack2(vhi.x, vhi.y);
    }
    const float g1lo = g1[lane], g1hi = g1[lane + 32];
    const float b1lo = b1[lane], b1hi = b1[lane + 32];
    const float g2lo = g2[lane], g2hi = g2[lane + 32];
    const float b2lo = b2[lane], b2hi = b2[lane + 32];
    const float w1x0 = w1[lane * 131 + 0], w1y0 = w1[lane * 131 + 1], w1z0 = w1[lane * 131 + 2];
    const float w1x1 = w1[(lane + 32) * 131 + 0], w1y1 = w1[(lane + 32) * 131 + 1], w1z1 = w1[(lane + 32) * 131 + 2];

    const float2* __restrict__ A2 = d_A[b];
    const int*    __restrict__ idxp = d_idx[b];

    for (int g = blockIdx.x * 8 + warp; g < G_TOT; g += gridDim.x * 8) {
        float gx = d_grid[g * 3 + 0], gy = d_grid[g * 3 + 1], gz = d_grid[g * 3 + 2];
        float qlo = w1x0 * gx + w1y0 * gy + w1z0 * gz;
        float qhi = w1x1 * gx + w1y1 * gy + w1z1 * gz;
        int kreg = idxp[g * NS + (lane & 15)];
        float mxA = -1e30f, mxB = -1e30f;
#pragma unroll 1
        for (int n = 0; n < NS; n++) {
            int k = __shfl_sync(0xffffffffu, kreg, n);
            float2 av = A2[k * 32 + lane];
            float hlo = fmaxf(fmaf(g1lo, av.x - qlo, b1lo), 0.f);
            float hhi = fmaxf(fmaf(g1hi, av.y - qhi, b1hi), 0.f);
            __syncwarp();
            hb[lane] = hlo;
            hb[lane + 32] = hhi;
            __syncwarp();
            unsigned long long a0 = 0ull, a1 = 0ull, c0 = 0ull, c1 = 0ull;
#pragma unroll
            for (int jj = 0; jj < 16; jj++) {
                float4 v = hb4[jj];
                unsigned long long h01 = pack2(v.x, v.y);
                unsigned long long h23 = pack2(v.z, v.w);
                fma2(a0, h01, w2lo[2 * jj]);
                fma2(a1, h23, w2lo[2 * jj + 1]);
                fma2(c0, h01, w2hi[2 * jj]);
                fma2(c1, h23, w2hi[2 * jj + 1]);
            }
            float2 pa0 = unpack2(a0), pa1 = unpack2(a1);
            float2 pc0 = unpack2(c0), pc1 = unpack2(c1);
            float dotA = (pa0.x + pa0.y) + (pa1.x + pa1.y);
            float dotB = (pc0.x + pc0.y) + (pc1.x + pc1.y);
            mxA = fmaxf(mxA, fmaf(g2lo, dotA, b2lo));
            mxB = fmaxf(mxB, fmaf(g2hi, dotB, b2hi));
        }
        // scatter into permuted red_in layout: flat = mi*16384 + cp*128 + ni
        int ni = g / N_GRIDP, mi = g % N_GRIDP;
        int cpA = b * 64 + lane;
        d_perm[mi * 16384 + cpA * 128 + ni] = fmaxf(mxA, 0.f);
        d_perm[mi * 16384 + (cpA + 32) * 128 + ni] = fmaxf(mxB, 0.f);
    }
}

// ---------------- k5: reduction GEMM layer1, split-K ----------------
// out_partial[ks][i][o] = sum_{j in chunk ks} perm[i][j] * W[o][j]
__global__ void __launch_bounds__(256) k_red1(const float* __restrict__ W)
{
    __shared__ float As[32][129];
    __shared__ float Bs[32][65];
    const int ob = blockIdx.x * 64;
    const int kbase = blockIdx.y * (K_RED / KSPLIT);   // 864
    const int tid = threadIdx.x;
    const int tx = tid & 15, ty = tid >> 4;

    float acc[8][4];
#pragma unroll
    for (int r = 0; r < 8; r++)
#pragma unroll
        for (int c = 0; c < 4; c++) acc[r][c] = 0.f;

    for (int kc = 0; kc < 864; kc += 32) {
        int k0 = kbase + kc;
#pragma unroll
        for (int r = 0; r < 16; r++) {
            int e = tid + 256 * r;
            int i = e >> 5, kk = e & 31;
            As[kk][i] = d_perm[i * K_RED + k0 + kk];
        }
#pragma unroll
        for (int r = 0; r < 8; r++) {
            int e = tid + 256 * r;
            int o = e >> 5, kk = e & 31;
            Bs[kk][o] = W[(ob + o) * K_RED + k0 + kk];
        }
        __syncthreads();
#pragma unroll
        for (int kk = 0; kk < 32; kk++) {
            float a[8], bb[4];
#pragma unroll
            for (int r = 0; r < 8; r++) a[r] = As[kk][ty * 8 + r];
#pragma unroll
            for (int c = 0; c < 4; c++) bb[c] = Bs[kk][tx * 4 + c];
#pragma unroll
            for (int r = 0; r < 8; r++)
#pragma unroll
                for (int c = 0; c < 4; c++) acc[r][c] = fmaf(a[r], bb[c], acc[r][c]);
        }
        __syncthreads();
    }
    float* outp = d_partial[blockIdx.y];
#pragma unroll
    for (int r = 0; r < 8; r++)
#pragma unroll
        for (int c = 0; c < 4; c++)
            outp[(ty * 8 + r) * 256 + ob + tx * 4 + c] = acc[r][c];
}

// ---------------- k6: partial reduce + bias + relu ----------------
__global__ void k_redfin(const float* __restrict__ b1)
{
    int t = blockIdx.x * 256 + threadIdx.x;     // 32768 total
    float s = b1[t & 255];
    for (int ks = 0; ks < KSPLIT; ks++) s += d_partial[ks][t];
    d_hbuf[t] = fmaxf(s, 0.f);
}

// ---------------- k7: layer2 256x256 + relu ----------------
__global__ void __launch_bounds__(256) k_red2(const float* __restrict__ W2, const float* __restrict__ b2,
                                              float* __restrict__ out)
{
    __shared__ float hs[256];
    int i = blockIdx.x;
    hs[threadIdx.x] = d_hbuf[i * 256 + threadIdx.x];
    __syncthreads();
    int o = threadIdx.x;
    float s = b2[o];
    const float* wr = W2 + o * 256;
#pragma unroll 8
    for (int c = 0; c < 256; c++) s = fmaf(hs[c], wr[c], s);
    out[i * 256 + o] = fmaxf(s, 0.f);
}

// ---------------- launch ----------------
extern "C" void kernel_launch(void* const* d_in, const int* in_sizes, int n_in,
                              void* d_out, int out_size)
{
    const float* wlh    = (const float*)d_in[0];
    const float* center = (const float*)d_in[1];
    const float* yaw    = (const float*)d_in[2];
    const float* u      = (const float*)d_in[3];
    const float* kp     = (const float*)d_in[4];   // (1,4096,3)
    const float* kf     = (const float*)d_in[5];   // (1,128,4096)
    const float* pn0_w1 = (const float*)d_in[6];
    const float* pn0_g1 = (const float*)d_in[7];
    const float* pn0_b1 = (const float*)d_in[8];
    const float* pn0_w2 = (const float*)d_in[9];
    const float* pn0_g2 = (const float*)d_in[10];
    const float* pn0_b2 = (const float*)d_in[11];
    const float* pn1_w1 = (const float*)d_in[12];
    const float* pn1_g1 = (const float*)d_in[13];
    const float* pn1_b1 = (const float*)d_in[14];
    const float* pn1_w2 = (const float*)d_in[15];
    const float* pn1_g2 = (const float*)d_in[16];
    const float* pn1_b2 = (const float*)d_in[17];
    const float* red_w1 = (const float*)d_in[18];
    const float* red_b1 = (const float*)d_in[19];
    const float* red_w2 = (const float*)d_in[20];
    const float* red_b2 = (const float*)d_in[21];
    float* out = (float*)d_out;

    k_grid<<<(G_TOT + 255) / 256, 256>>>(wlh, center, yaw, u);
    k_A<<<dim3(16, 2), dim3(32, 8)>>>(kp, kf, pn0_w1, pn1_w1);
    k_ball<<<G_TOT / 128, 128>>>(kp);
    k_branch<<<dim3(74, 2), 256>>>(pn0_w1, pn0_g1, pn0_b1, pn0_w2, pn0_g2, pn0_b2,
                                   pn1_w1, pn1_g1, pn1_b1, pn1_w2, pn1_g2, pn1_b2);
    k_red1<<<dim3(4, KSPLIT), 256>>>(red_w1);
    k_redfin<<<128, 256>>>(red_b1);
    k_red2<<<128, 256>>>(red_w2, red_b2, out);
}